// round 8
// baseline (speedup 1.0000x reference)
#include <cuda_runtime.h>
#include <cstdint>

// Problem constants (fixed by the reference):
// b=2, h=32, n=8192, d=128, e=128, BLOCK=64, num_block=128
// grid = b*h*num_block = 8192 CTAs; each computes one [64x128] = Q[64x128] @ KV[128x128]
// then out = output_in + decay(row) * acc.

#define QSTRIDE 132   // 128 + 4 pad  (A-frag LDS conflict-free: bank = gid*4+tig)
#define KVSTRIDE 136  // 128 + 8 pad  (B-frag LDS conflict-free: bank = tig*8+gid)
#define SMEM_BYTES ((64 * QSTRIDE + 128 * KVSTRIDE) * 4)

__global__ __launch_bounds__(128, 2)
void lightning_inter_kernel(const float* __restrict__ q,
                            const float* __restrict__ outp,
                            const float* __restrict__ s,
                            const float* __restrict__ kv,
                            float* __restrict__ out)
{
    extern __shared__ float sm[];
    float* Qs  = sm;                 // 64  x QSTRIDE
    float* KVs = sm + 64 * QSTRIDE;  // 128 x KVSTRIDE

    const int c  = blockIdx.x;
    const int m  = c & 127;     // block index within sequence (num_block = 128)
    const int bh = c >> 7;      // fused (b,h)
    const int h  = bh & 31;

    const size_t row0 = ((size_t)bh * 8192 + (size_t)m * 64) * 128; // element offset of tile
    const float* qg  = q    + row0;
    const float* og  = outp + row0;
    float*       outg = out + row0;
    const float* kvg = kv + ((size_t)bh * 128 + m) * 16384;

    const int tid = threadIdx.x;

    // ---- Stage Q (64x128) and KV (128x128) into smem via cp.async (16B) ----
    #pragma unroll 4
    for (int i = tid; i < 2048; i += 128) {           // Q: 2048 float4
        int r = i >> 5, c4 = i & 31;
        uint32_t dst = (uint32_t)__cvta_generic_to_shared(Qs + r * QSTRIDE + c4 * 4);
        asm volatile("cp.async.cg.shared.global [%0], [%1], 16;\n"
                     :: "r"(dst), "l"(qg + r * 128 + c4 * 4));
    }
    #pragma unroll 4
    for (int i = tid; i < 4096; i += 128) {           // KV: 4096 float4
        int r = i >> 5, c4 = i & 31;
        uint32_t dst = (uint32_t)__cvta_generic_to_shared(KVs + r * KVSTRIDE + c4 * 4);
        asm volatile("cp.async.cg.shared.global [%0], [%1], 16;\n"
                     :: "r"(dst), "l"(kvg + r * 128 + c4 * 4));
    }
    asm volatile("cp.async.commit_group;\n" ::: "memory");
    asm volatile("cp.async.wait_group 0;\n" ::: "memory");
    __syncthreads();

    // ---- TF32 mma.sync m16n8k8: warp w owns rows [w*16, w*16+16), all 128 cols ----
    const int warp = tid >> 5;
    const int lane = tid & 31;
    const int gid  = lane >> 2;   // groupID (0..7)
    const int tig  = lane & 3;    // thread-in-group (0..3)
    const int m0   = warp * 16;

    float acc[16][4];
    #pragma unroll
    for (int i = 0; i < 16; i++)
        #pragma unroll
        for (int j = 0; j < 4; j++) acc[i][j] = 0.f;

    #pragma unroll
    for (int ks = 0; ks < 16; ks++) {
        const int k0 = ks * 8;
        // A fragment (row-major m16k8)
        const float* Ar0 = Qs + (m0 + gid) * QSTRIDE + k0;
        const float* Ar1 = Qs + (m0 + gid + 8) * QSTRIDE + k0;
        uint32_t a0 = __float_as_uint(Ar0[tig]);
        uint32_t a1 = __float_as_uint(Ar1[tig]);
        uint32_t a2 = __float_as_uint(Ar0[tig + 4]);
        uint32_t a3 = __float_as_uint(Ar1[tig + 4]);
        // B fragment base pointers (col-major k8n8 view of KV[k][n])
        const float* B0 = KVs + (k0 + tig) * KVSTRIDE + gid;
        const float* B1 = KVs + (k0 + tig + 4) * KVSTRIDE + gid;
        #pragma unroll
        for (int nt = 0; nt < 16; nt++) {
            uint32_t b0 = __float_as_uint(B0[nt * 8]);
            uint32_t b1 = __float_as_uint(B1[nt * 8]);
            asm volatile(
                "mma.sync.aligned.m16n8k8.row.col.f32.tf32.tf32.f32 "
                "{%0,%1,%2,%3},{%4,%5,%6,%7},{%8,%9},{%0,%1,%2,%3};\n"
                : "+f"(acc[nt][0]), "+f"(acc[nt][1]),
                  "+f"(acc[nt][2]), "+f"(acc[nt][3])
                : "r"(a0), "r"(a1), "r"(a2), "r"(a3), "r"(b0), "r"(b1));
        }
    }

    // ---- Epilogue: out = output_in + exp(-s*(pos+1)) * acc ----
    const float sh = s[h];
    const int r0 = m0 + gid;        // position within block (BM == BLOCK == 64)
    const int r1 = r0 + 8;
    const float d0 = expf(-sh * (float)(r0 + 1));
    const float d1 = expf(-sh * (float)(r1 + 1));

    #pragma unroll
    for (int nt = 0; nt < 16; nt++) {
        const int col = nt * 8 + 2 * tig;
        float2 v0 = *(const float2*)(og + (size_t)r0 * 128 + col);
        float2 v1 = *(const float2*)(og + (size_t)r1 * 128 + col);
        v0.x += d0 * acc[nt][0];
        v0.y += d0 * acc[nt][1];
        v1.x += d1 * acc[nt][2];
        v1.y += d1 * acc[nt][3];
        *(float2*)(outg + (size_t)r0 * 128 + col) = v0;
        *(float2*)(outg + (size_t)r1 * 128 + col) = v1;
    }
}

extern "C" void kernel_launch(void* const* d_in, const int* in_sizes, int n_in,
                              void* d_out, int out_size)
{
    const float* q    = (const float*)d_in[0]; // [2,32,8192,128]
    const float* outp = (const float*)d_in[1]; // [2,32,8192,128]
    const float* s    = (const float*)d_in[2]; // [32]
    const float* kv   = (const float*)d_in[3]; // [2,32,128,128,128]
    float* out = (float*)d_out;

    cudaFuncSetAttribute(lightning_inter_kernel,
                         cudaFuncAttributeMaxDynamicSharedMemorySize, SMEM_BYTES);

    // grid = b*h*num_block = 2*32*128 = 8192
    lightning_inter_kernel<<<8192, 128, SMEM_BYTES>>>(q, outp, s, kv, out);
}